// round 1
// baseline (speedup 1.0000x reference)
#include <cuda_runtime.h>
#include <cstdint>

#define NA 50000
#define NE 500000
#define H  128
#define R  20
#define H3 (3*H)

static constexpr float PI_F = 3.14159265358979323846f;
static constexpr float PI_OVER_CUT = PI_F / 6.0f;   // pi / CUTOFF

// ---------------- scratch (static device globals; no allocations) ------------
__device__ float g_ns   [NA * H];        // node scalar
__device__ float g_nv   [NA * H3];       // node vector [N,3,H]
__device__ float g_dnv  [NA * H3];       // vector message accumulator (delta)
__device__ float g_s    [NA * H3];       // message MLP output s [N,3H]
__device__ float g_a    [NA * H3];       // update MLP output a [N,3H]
__device__ float g_hid  [NA * H];        // MLP hidden scratch
__device__ float g_mlpin[NA * 2 * H];    // concat(ns, Vnorm)
__device__ float g_Uv   [NA * H3];
__device__ float g_Vv   [NA * H3];
__device__ float g_rbf  [NE * R];        // rbf * fcut
__device__ float g_unit [NE * 3];
__device__ float g_fcut [NE];
__device__ float g_dist [NE];

__device__ __forceinline__ float silu_f(float x) { return x / (1.0f + __expf(-x)); }

// ---------------- init: ns = embed[z], nv = 0, dnv = 0 -----------------------
__global__ void init_kernel(const int* __restrict__ z, const float* __restrict__ embed)
{
    int idx = blockIdx.x * blockDim.x + threadIdx.x;
    int total = NA * H3;
    for (int i = idx; i < total; i += gridDim.x * blockDim.x) {
        g_nv[i]  = 0.0f;
        g_dnv[i] = 0.0f;
        if (i < NA * H) {
            int n = i / H, h = i - n * H;
            g_ns[i] = embed[z[n] * H + h];
        }
    }
}

// ---------------- edge geometry: dist, unit, fcut, rbf*fcut ------------------
__global__ void edge_geom_kernel(const float* __restrict__ pos,
                                 const float* __restrict__ cell,
                                 const int*   __restrict__ eidx,
                                 const int*   __restrict__ coff)
{
    int e = blockIdx.x * blockDim.x + threadIdx.x;
    if (e >= NE) return;
    int row = eidx[e];
    int col = eidx[NE + e];
    float ox = (float)coff[e * 3 + 0];
    float oy = (float)coff[e * 3 + 1];
    float oz = (float)coff[e * 3 + 2];
    // offsets @ cell : out[j] = sum_i off[i] * cell[i][j]
    float offx = ox * cell[0] + oy * cell[3] + oz * cell[6];
    float offy = ox * cell[1] + oy * cell[4] + oz * cell[7];
    float offz = ox * cell[2] + oy * cell[5] + oz * cell[8];
    float dx = pos[row * 3 + 0] - pos[col * 3 + 0] + offx;
    float dy = pos[row * 3 + 1] - pos[col * 3 + 1] + offy;
    float dz = pos[row * 3 + 2] - pos[col * 3 + 2] + offz;
    float d  = sqrtf(dx * dx + dy * dy + dz * dz);
    float inv = 1.0f / d;
    g_dist[e] = d;
    g_unit[e * 3 + 0] = dx * inv;
    g_unit[e * 3 + 1] = dy * inv;
    g_unit[e * 3 + 2] = dz * inv;
    float fc = (d < 6.0f) ? 0.5f * (cosf(PI_F * d * (1.0f / 6.0f)) + 1.0f) : 0.0f;
    g_fcut[e] = fc;
#pragma unroll
    for (int r = 0; r < R; r++) {
        float arg = d * (float)(r + 1) * PI_OVER_CUT;
        g_rbf[e * R + r] = sinf(arg) * inv * fc;   // fold fcut into rbf
    }
}

// ---------------- generic tiled SGEMM: C = act(A[M,K] @ B[K,N] + bias) -------
// Requirements: K % 16 == 0, N % 64 == 0 (true for all call sites).
template <int ACT>
__global__ __launch_bounds__(256)
void gemm_kernel(const float* __restrict__ A, const float* __restrict__ B,
                 const float* __restrict__ bias, float* __restrict__ C,
                 int M, int N, int K)
{
    constexpr int BM = 64, BN = 64, BK = 16;
    __shared__ float As[BM][BK + 1];
    __shared__ float Bs[BK][BN + 4];

    int bm = blockIdx.x * BM;
    int bn = blockIdx.y * BN;
    int tid = threadIdx.x;
    int tx = tid & 15;        // 0..15 -> 4 cols each
    int ty = tid >> 4;        // 0..15 -> 4 rows each

    float acc[4][4] = {};

    for (int k0 = 0; k0 < K; k0 += BK) {
        // load A tile (64x16), 4 contiguous floats per thread
        {
            int idx = tid * 4;
            int r = idx >> 4, c = idx & 15;
            int grow = bm + r;
            float4 v = make_float4(0.f, 0.f, 0.f, 0.f);
            if (grow < M)
                v = *reinterpret_cast<const float4*>(A + (size_t)grow * K + k0 + c);
            As[r][c] = v.x; As[r][c + 1] = v.y; As[r][c + 2] = v.z; As[r][c + 3] = v.w;
        }
        // load B tile (16x64)
        {
            int idx = tid * 4;
            int r = idx >> 6, c = idx & 63;
            float4 v = *reinterpret_cast<const float4*>(B + (size_t)(k0 + r) * N + bn + c);
            Bs[r][c] = v.x; Bs[r][c + 1] = v.y; Bs[r][c + 2] = v.z; Bs[r][c + 3] = v.w;
        }
        __syncthreads();
#pragma unroll
        for (int kk = 0; kk < BK; kk++) {
            float a[4], b[4];
#pragma unroll
            for (int i = 0; i < 4; i++) a[i] = As[ty * 4 + i][kk];
#pragma unroll
            for (int j = 0; j < 4; j++) b[j] = Bs[kk][tx * 4 + j];
#pragma unroll
            for (int i = 0; i < 4; i++)
#pragma unroll
                for (int j = 0; j < 4; j++)
                    acc[i][j] = fmaf(a[i], b[j], acc[i][j]);
        }
        __syncthreads();
    }

#pragma unroll
    for (int i = 0; i < 4; i++) {
        int grow = bm + ty * 4 + i;
        if (grow >= M) continue;
#pragma unroll
        for (int j = 0; j < 4; j++) {
            int gc = bn + tx * 4 + j;
            float v = acc[i][j] + (bias ? bias[gc] : 0.0f);
            if (ACT == 1) v = silu_f(v);
            C[(size_t)grow * N + gc] = v;
        }
    }
}

// ---------------- message kernel (per-edge, 128 threads = channels) ----------
#define EPB 16
__global__ __launch_bounds__(128)
void msg_kernel(const float* __restrict__ Wf, const float* __restrict__ bf,
                const int* __restrict__ eidx)
{
    __shared__ float sW[R * H3];
    __shared__ float sb[H3];
    int t = threadIdx.x;
    for (int i = t; i < R * H3; i += 128) sW[i] = Wf[i];
    for (int i = t; i < H3; i += 128) sb[i] = bf[i];
    __syncthreads();

    int e0 = blockIdx.x * EPB;
    for (int ei = 0; ei < EPB; ei++) {
        int e = e0 + ei;
        if (e >= NE) break;
        int row = eidx[e];
        int col = eidx[NE + e];
        float fc = g_fcut[e];
        float ux = g_unit[e * 3 + 0];
        float uy = g_unit[e * 3 + 1];
        float uz = g_unit[e * 3 + 2];

        float f0 = sb[t] * fc;
        float f1 = sb[t + H] * fc;
        float f2 = sb[t + 2 * H] * fc;
#pragma unroll
        for (int r = 0; r < R; r++) {
            float rb = g_rbf[e * R + r];          // rbf * fcut (broadcast)
            f0 = fmaf(rb, sW[r * H3 + t], f0);
            f1 = fmaf(rb, sW[r * H3 + t + H], f1);
            f2 = fmaf(rb, sW[r * H3 + t + 2 * H], f2);
        }
        const float* sc = g_s + (size_t)col * H3;
        float gate_sv = f0 * sc[t];
        float gate_ev = f1 * sc[t + H];
        float msg_s   = f2 * sc[t + 2 * H];

        atomicAdd(&g_ns[(size_t)row * H + t], msg_s);

        const float* nvc = g_nv  + (size_t)col * H3;
        float*       dnr = g_dnv + (size_t)row * H3;
        atomicAdd(&dnr[t],         fmaf(nvc[t],         gate_sv, gate_ev * ux));
        atomicAdd(&dnr[H + t],     fmaf(nvc[H + t],     gate_sv, gate_ev * uy));
        atomicAdd(&dnr[2 * H + t], fmaf(nvc[2 * H + t], gate_sv, gate_ev * uz));
    }
}

// ---------------- nv += dnv; dnv = 0 ----------------------------------------
__global__ void apply_dnv_kernel()
{
    int idx = blockIdx.x * blockDim.x + threadIdx.x;
    int total = NA * H3;
    for (int i = idx; i < total; i += gridDim.x * blockDim.x) {
        g_nv[i] += g_dnv[i];
        g_dnv[i] = 0.0f;
    }
}

// ---------------- Vnorm + concat into mlp_in ---------------------------------
__global__ void vnorm_concat_kernel()
{
    int idx = blockIdx.x * blockDim.x + threadIdx.x;
    if (idx >= NA * H) return;
    int n = idx / H, h = idx - n * H;
    float v0 = g_Vv[(size_t)n * H3 + h];
    float v1 = g_Vv[(size_t)n * H3 + H + h];
    float v2 = g_Vv[(size_t)n * H3 + 2 * H + h];
    float nrm = sqrtf(v0 * v0 + v1 * v1 + v2 * v2);
    g_mlpin[(size_t)n * 2 * H + h]     = g_ns[idx];
    g_mlpin[(size_t)n * 2 * H + H + h] = nrm;
}

// ---------------- final update block -----------------------------------------
__global__ void update_final_kernel()
{
    int idx = blockIdx.x * blockDim.x + threadIdx.x;
    if (idx >= NA * H) return;
    int n = idx / H, h = idx - n * H;
    size_t b3 = (size_t)n * H3;
    float a_vv = g_a[b3 + h];
    float a_sv = g_a[b3 + H + h];
    float a_ss = g_a[b3 + 2 * H + h];
    float uv0 = g_Uv[b3 + h], uv1 = g_Uv[b3 + H + h], uv2 = g_Uv[b3 + 2 * H + h];
    float vv0 = g_Vv[b3 + h], vv1 = g_Vv[b3 + H + h], vv2 = g_Vv[b3 + 2 * H + h];
    g_nv[b3 + h]         += a_vv * uv0;
    g_nv[b3 + H + h]     += a_vv * uv1;
    g_nv[b3 + 2 * H + h] += a_vv * uv2;
    float inner = uv0 * vv0 + uv1 * vv1 + uv2 * vv2;
    g_ns[idx] += inner * a_sv + a_ss;
}

// ---------------- head final reduce: [N,64] @ [64,1] + b ---------------------
__global__ __launch_bounds__(128)
void head_reduce_kernel(const float* __restrict__ W2, const float* __restrict__ b2,
                        float* __restrict__ out)
{
    int warp = threadIdx.x >> 5;
    int lane = threadIdx.x & 31;
    int n = blockIdx.x * 4 + warp;
    if (n >= NA) return;
    float s = g_hid[(size_t)n * 64 + lane]      * W2[lane]
            + g_hid[(size_t)n * 64 + 32 + lane] * W2[32 + lane];
#pragma unroll
    for (int off = 16; off > 0; off >>= 1)
        s += __shfl_xor_sync(0xFFFFFFFFu, s, off);
    if (lane == 0) out[n] = s + b2[0];
}

// ---------------- output tail: pos, edge_index (as float), dist --------------
__global__ void write_outputs_kernel(const float* __restrict__ pos,
                                     const int* __restrict__ eidx,
                                     float* __restrict__ out)
{
    int idx = blockIdx.x * blockDim.x + threadIdx.x;
    const int total = 3 * NA + 2 * NE + NE;
    for (int i = idx; i < total; i += gridDim.x * blockDim.x) {
        if (i < 3 * NA) {
            out[NA + i] = pos[i];
        } else if (i < 3 * NA + 2 * NE) {
            int j = i - 3 * NA;
            out[4 * NA + j] = (float)eidx[j];
        } else {
            int j = i - 3 * NA - 2 * NE;
            out[4 * NA + 2 * NE + j] = g_dist[j];
        }
    }
}

// =============================================================================
extern "C" void kernel_launch(void* const* d_in, const int* in_sizes, int n_in,
                              void* d_out, int out_size)
{
    const int*   z     = (const int*)  d_in[0];
    const float* pos   = (const float*)d_in[1];
    const float* cell  = (const float*)d_in[2];
    const int*   eidx  = (const int*)  d_in[3];
    const int*   coff  = (const int*)  d_in[4];
    const float* embed = (const float*)d_in[5];
    const float* mfW   = (const float*)d_in[6];
    const float* mfb   = (const float*)d_in[7];
    const float* mW1   = (const float*)d_in[8];
    const float* mb1   = (const float*)d_in[9];
    const float* mW2   = (const float*)d_in[10];
    const float* mb2   = (const float*)d_in[11];
    const float* uU    = (const float*)d_in[12];
    const float* uV    = (const float*)d_in[13];
    const float* uW1   = (const float*)d_in[14];
    const float* ub1   = (const float*)d_in[15];
    const float* uW2   = (const float*)d_in[16];
    const float* ub2   = (const float*)d_in[17];
    const float* hW1   = (const float*)d_in[18];
    const float* hb1   = (const float*)d_in[19];
    const float* hW2   = (const float*)d_in[20];
    const float* hb2   = (const float*)d_in[21];
    float* out = (float*)d_out;

    float *p_ns, *p_nv, *p_s, *p_a, *p_hid, *p_mlpin, *p_Uv, *p_Vv;
    cudaGetSymbolAddress((void**)&p_ns,    g_ns);
    cudaGetSymbolAddress((void**)&p_nv,    g_nv);
    cudaGetSymbolAddress((void**)&p_s,     g_s);
    cudaGetSymbolAddress((void**)&p_a,     g_a);
    cudaGetSymbolAddress((void**)&p_hid,   g_hid);
    cudaGetSymbolAddress((void**)&p_mlpin, g_mlpin);
    cudaGetSymbolAddress((void**)&p_Uv,    g_Uv);
    cudaGetSymbolAddress((void**)&p_Vv,    g_Vv);

    init_kernel<<<1024, 256>>>(z, embed);
    edge_geom_kernel<<<(NE + 255) / 256, 256>>>(pos, cell, eidx, coff);

    dim3 gN128((NA + 63) / 64, 2);        // [N,128] outputs
    dim3 gN384((NA + 63) / 64, 6);        // [N,384] outputs
    dim3 g3N128((3 * NA + 63) / 64, 2);   // [3N,128] outputs
    dim3 gN64((NA + 63) / 64, 1);         // [N,64] output

    for (int l = 0; l < 3; l++) {
        // message MLP: s = silu(ns@W1+b1)@W2+b2
        gemm_kernel<1><<<gN128, 256>>>(p_ns, mW1 + (size_t)l * H * H, mb1 + (size_t)l * H,
                                       p_hid, NA, H, H);
        gemm_kernel<0><<<gN384, 256>>>(p_hid, mW2 + (size_t)l * H * H3, mb2 + (size_t)l * H3,
                                       p_s, NA, H3, H);
        // edge messages (scalar into ns directly, vector into dnv)
        msg_kernel<<<(NE + EPB - 1) / EPB, 128>>>(mfW + (size_t)l * R * H3,
                                                  mfb + (size_t)l * H3, eidx);
        apply_dnv_kernel<<<1024, 256>>>();

        // update block
        gemm_kernel<0><<<g3N128, 256>>>(p_nv, uU + (size_t)l * H * H, nullptr,
                                        p_Uv, 3 * NA, H, H);
        gemm_kernel<0><<<g3N128, 256>>>(p_nv, uV + (size_t)l * H * H, nullptr,
                                        p_Vv, 3 * NA, H, H);
        vnorm_concat_kernel<<<(NA * H + 255) / 256, 256>>>();
        gemm_kernel<1><<<gN128, 256>>>(p_mlpin, uW1 + (size_t)l * 2 * H * H, ub1 + (size_t)l * H,
                                       p_hid, NA, H, 2 * H);
        gemm_kernel<0><<<gN384, 256>>>(p_hid, uW2 + (size_t)l * H * H3, ub2 + (size_t)l * H3,
                                       p_a, NA, H3, H);
        update_final_kernel<<<(NA * H + 255) / 256, 256>>>();
    }

    // head
    gemm_kernel<1><<<gN64, 256>>>(p_ns, hW1, hb1, p_hid, NA, 64, H);
    head_reduce_kernel<<<(NA + 3) / 4, 128>>>(hW2, hb2, out);

    write_outputs_kernel<<<2048, 256>>>(pos, eidx, out);
}